// round 5
// baseline (speedup 1.0000x reference)
#include <cuda_runtime.h>
#include <cstdint>

#define B_ 2
#define S_ 1024
#define D_ 128

typedef unsigned long long u64;

// ---------------- scratch ----------------
__device__ float g_Qt[B_*D_*S_];     // q' = 1-Q, transposed [b][d][s]
__device__ float g_Kt[B_*D_*S_];     // k' = 1-K, transposed [b][d][s]
__device__ float g_sumK[B_*S_];      // sum_d K (original) per row
__device__ float g_V[B_*S_*D_];      // V [b][s][d]
__device__ float g_Z[B_*S_];         // row sums of E' = exp(10T)-1
__device__ float g_totV[B_*D_];      // sum_s V

__device__ __forceinline__ u64 pack2(float a, float b){
  u64 r; asm("mov.b64 %0, {%1, %2};" : "=l"(r) : "f"(a), "f"(b)); return r;
}
__device__ __forceinline__ void unpack2(u64 v, float& a, float& b){
  asm("mov.b64 {%0, %1}, %2;" : "=f"(a), "=f"(b) : "l"(v));
}
__device__ __forceinline__ u64 fma2(u64 a, u64 b, u64 c){
  u64 d; asm("fma.rn.f32x2 %0, %1, %2, %3;" : "=l"(d) : "l"(a), "l"(b), "l"(c)); return d;
}

// ---------------- K1: QKV (+ zero out/Z + zero att upper triangle) -------
// 128 blocks x 512 threads, 16 seq rows per block.
__global__ void __launch_bounds__(512) k_qkv(
    const float* __restrict__ x,
    const float* __restrict__ wq, const float* __restrict__ bq,
    const float* __restrict__ wk, const float* __restrict__ bk,
    const float* __restrict__ wv, const float* __restrict__ bv,
    float* __restrict__ outp){
  extern __shared__ float sm[];
  float* ws = sm;                 // [2][3][32][128]  = 24576 floats
  float* xs = sm + 24576;         // [16][128]        = 2048 floats
  __shared__ float wred[16][4];

  int t = threadIdx.x;
  int o = t & 127;                // output dim
  int h = t >> 7;                 // row group (4 rows each), 0..3
  int s0 = blockIdx.x*16;
  int b  = s0 >> 10;
  int sl = s0 & 1023;

  // zero the out region (65536 f4 over 128 blocks) + g_Z
  ((float4*)outp)[blockIdx.x*512 + t] = make_float4(0.f,0.f,0.f,0.f);
  if (t < 16) g_Z[blockIdx.x*16 + t] = 0.f;

  // zero the att upper region not covered by any compute tile:
  // rows sl..sl+15 share q0 = sl & ~127; cols [q0+128, 1024)
  {
    float* att = outp + B_*S_*D_;
    int q0u = sl & ~127;
    int start = q0u + 128;
    if (start < 1024){
      int w4 = (1024 - start) >> 2;      // <= 224
      float4 z4 = make_float4(0.f,0.f,0.f,0.f);
      #pragma unroll
      for (int row=0; row<16; row++){
        if (t < w4)
          ((float4*)(att + (b*S_ + sl + row)*S_ + start))[t] = z4;
      }
    }
  }

  // stage x tile [16 s][128 d] row-major (1 f4/thread, conflict-free)
  ((float4*)xs)[t] = ((const float4*)(x + s0*D_))[t];

  const float4* wq4 = (const float4*)wq;
  const float4* wk4 = (const float4*)wk;
  const float4* wv4 = (const float4*)wv;
  float4* ws4 = (float4*)ws;

  // stage chunk 0 into buffer 0
  #pragma unroll
  for (int j=0;j<6;j++){
    int i = t + j*512;            // 0..3071 f4 of a chunk
    int m = i >> 10, r = i & 1023;
    const float4* src = (m==0)? wq4 : (m==1)? wk4 : wv4;
    ws4[i] = src[((r>>5))*32 + (r&31)];
  }
  __syncthreads();

  u64 aq[4], ak[4], av[4];
  #pragma unroll
  for (int jr=0;jr<4;jr++){ aq[jr]=0ull; ak[jr]=0ull; av[jr]=0ull; }

  #pragma unroll 1
  for (int c=0; c<4; c++){
    if (c < 3){
      int f = (c+1)&1;
      #pragma unroll
      for (int j=0;j<6;j++){
        int i = t + j*512;
        int m = i >> 10, r = i & 1023;
        const float4* src = (m==0)? wq4 : (m==1)? wk4 : wv4;
        ws4[f*3072 + i] = src[((c+1)*32 + (r>>5))*32 + (r&31)];
      }
    }
    const float* wb = ws + (c&1)*12288;
    #pragma unroll 4
    for (int dp=0; dp<16; dp++){
      int d0 = dp*2;
      u64 xp0 = *(const u64*)&xs[(h*4+0)*128 + c*32 + d0];
      u64 xp1 = *(const u64*)&xs[(h*4+1)*128 + c*32 + d0];
      u64 xp2 = *(const u64*)&xs[(h*4+2)*128 + c*32 + d0];
      u64 xp3 = *(const u64*)&xs[(h*4+3)*128 + c*32 + d0];
      u64 wqp = pack2(wb[          d0*128 + o], wb[          (d0+1)*128 + o]);
      u64 wkp = pack2(wb[ 4096 +   d0*128 + o], wb[ 4096 +   (d0+1)*128 + o]);
      u64 wvp = pack2(wb[ 8192 +   d0*128 + o], wb[ 8192 +   (d0+1)*128 + o]);
      aq[0]=fma2(wqp,xp0,aq[0]); aq[1]=fma2(wqp,xp1,aq[1]);
      aq[2]=fma2(wqp,xp2,aq[2]); aq[3]=fma2(wqp,xp3,aq[3]);
      ak[0]=fma2(wkp,xp0,ak[0]); ak[1]=fma2(wkp,xp1,ak[1]);
      ak[2]=fma2(wkp,xp2,ak[2]); ak[3]=fma2(wkp,xp3,ak[3]);
      av[0]=fma2(wvp,xp0,av[0]); av[1]=fma2(wvp,xp1,av[1]);
      av[2]=fma2(wvp,xp2,av[2]); av[3]=fma2(wvp,xp3,av[3]);
    }
    __syncthreads();
  }

  float bqv = bq[o], bkv = bk[o], bvv = bv[o];
  float qv[4], kv[4], vv[4];
  #pragma unroll
  for (int jr=0;jr<4;jr++){
    float a0,a1;
    unpack2(aq[jr],a0,a1); qv[jr] = a0+a1+bqv;
    unpack2(ak[jr],a0,a1); kv[jr] = a0+a1+bkv;
    unpack2(av[jr],a0,a1); vv[jr] = a0+a1+bvv;
  }
  // primes: q' = 1 - sigmoid(z) = 1/(1+exp(z))
  #pragma unroll
  for (int jr=0;jr<4;jr++){
    qv[jr] = 1.f/(1.f+__expf(qv[jr]));
    kv[jr] = 1.f/(1.f+__expf(kv[jr]));
  }

  // V stores (coalesced)
  #pragma unroll
  for (int jr=0;jr<4;jr++) g_V[(s0 + h*4 + jr)*D_ + o] = vv[jr];

  // transposed Q'/K' stores
  ((float4*)(g_Qt + b*D_*S_ + o*S_ + sl + h*4))[0] =
      make_float4(qv[0],qv[1],qv[2],qv[3]);
  ((float4*)(g_Kt + b*D_*S_ + o*S_ + sl + h*4))[0] =
      make_float4(kv[0],kv[1],kv[2],kv[3]);

  // sumK = 128 - sum_d k'
  float red[4] = {kv[0],kv[1],kv[2],kv[3]};
  #pragma unroll
  for (int off=16; off>=1; off>>=1){
    #pragma unroll
    for (int jr=0;jr<4;jr++) red[jr] += __shfl_xor_sync(0xffffffffu, red[jr], off);
  }
  int w = t >> 5;
  if ((t & 31) == 0){
    #pragma unroll
    for (int jr=0;jr<4;jr++) wred[w][jr] = red[jr];
  }
  __syncthreads();
  if (t < 16){
    int r = t, hh = r >> 2, jr = r & 3;
    float tot = wred[hh*4+0][jr]+wred[hh*4+1][jr]+wred[hh*4+2][jr]+wred[hh*4+3][jr];
    g_sumK[s0 + r] = 128.f - tot;
  }
}

// ---------------- K2: fused truth + E' + Z + E'@V ------------------------
// 290 blocks: 0..287 compute tiles (128q x 32k, d-split), 288..289 totV
// 41KB dynamic smem -> 2 blocks/SM, 32 warps/SM
__global__ void __launch_bounds__(512,2) k_main(float* __restrict__ outp){
  extern __shared__ float sm[];
  float* Qts = sm;               // [64 d][128 q]  8192 fl
  float* Kts = sm + 8192;        // [64 d][32 k]   2048 fl
  float* sKs = sm + 10240;       // [32]
  // phase-3 reuse (all under the 8192-fl Qts region + headroom):
  float* Es  = sm;               // [32 k][132 q-pitch] 4224 fl
  float* Vs  = sm + 4352;        // [32 k][128 d]       4096 fl
  int bid = blockIdx.x;
  int t = threadIdx.x;
  float* att = outp + B_*S_*D_;

  if (bid >= 288){
    // ---- totV reduction, one block per batch ----
    int b = bid - 288;
    int d = t & 127, g = t >> 7;   // 4 groups x 256 rows
    const float* Vb = g_V + b*S_*D_;
    float a = 0.f;
    for (int s = g*256; s < (g+1)*256; s++) a += Vb[s*D_ + d];
    sm[g*128 + d] = a;
    __syncthreads();
    if (t < 128)
      g_totV[b*D_ + t] = sm[t] + sm[128+t] + sm[256+t] + sm[384+t];
    return;
  }

  // ---- compute tile ----
  int b = bid / 144, r = bid - b*144;
  int qt = 0;
  while (2*(qt+1)*(qt+2) <= r) qt++;
  int kt = r - 2*qt*(qt+1);
  int q0 = qt*128, k0 = kt*32;
  int tx = t & 15, ty = t >> 4;    // ty 0..31

  const float4* Qg = (const float4*)(g_Qt + b*D_*S_);
  const float4* Kg = (const float4*)(g_Kt + b*D_*S_);
  const float4* Vg = (const float4*)(g_V + b*S_*D_);

  // prefetch V tile (32 k x 128 d = 1024 f4) into registers
  float4 vpre[2];
  #pragma unroll
  for (int it=0; it<2; it++){
    int i = t + it*512;
    vpre[it] = Vg[(k0 + (i>>5))*32 + (i&31)];
  }

  float4* Qts4 = (float4*)Qts;
  float4* Kts4 = (float4*)Kts;

  float acc[4][2];
  #pragma unroll
  for (int i=0;i<4;i++){ acc[i][0]=0.f; acc[i][1]=0.f; }

  // phase 1: two d-halves of 64
  #pragma unroll 1
  for (int hf=0; hf<2; hf++){
    #pragma unroll
    for (int it=0; it<4; it++){
      int i = t + it*512;                   // 2048 f4 (Q half)
      Qts4[i] = Qg[(hf*64 + (i>>5))*256 + (q0>>2) + (i&31)];
    }
    if (t < 512){                           // 512 f4 (K half)
      int i = t;
      Kts4[i] = Kg[(hf*64 + (i>>3))*256 + (k0>>2) + (i&7)];
    }
    if (hf==0 && t < 32) sKs[t] = g_sumK[b*S_ + k0 + t];
    __syncthreads();

    #pragma unroll 4
    for (int d=0; d<64; d++){
      float4 qa = Qts4[d*32 + ty];
      float2 kf = *(const float2*)&Kts[d*32 + tx*2];
      float qq[4] = {qa.x,qa.y,qa.z,qa.w};
      #pragma unroll
      for (int i=0;i<4;i++){
        asm("{.reg .f32 m; set.le.f32.f32 m, %1, %2; fma.rn.f32 %0, m, %1, %0;}"
            : "+f"(acc[i][0]) : "f"(kf.x), "f"(qq[i]));
        asm("{.reg .f32 m; set.le.f32.f32 m, %1, %2; fma.rn.f32 %0, m, %1, %0;}"
            : "+f"(acc[i][1]) : "f"(kf.y), "f"(qq[i]));
      }
    }
    __syncthreads();
  }

  // phase 2: T, att store, E' = exp(10T)-1, Z partial
  const float inv = 1.f/128.f;
  float e[4][2];
  #pragma unroll
  for (int i=0;i<4;i++){
    int qg = q0 + ty*4 + i;
    float zrow = 0.f;
    float tt[2];
    #pragma unroll
    for (int j=0;j<2;j++){
      int kg = k0 + tx*2 + j;
      float T = (acc[i][j] + sKs[tx*2+j]) * inv;
      bool val = (kg <= qg);
      T = val ? T : 0.f;
      float ee = val ? (__expf(10.f*T) - 1.f) : 0.f;
      tt[j] = T; e[i][j] = ee; zrow += ee;
    }
    ((float2*)(att + (b*S_ + qg)*S_ + k0 + tx*2))[0] = make_float2(tt[0], tt[1]);
    #pragma unroll
    for (int off=8; off>=1; off>>=1)
      zrow += __shfl_xor_sync(0xffffffffu, zrow, off);
    if (tx == 0) atomicAdd(&g_Z[b*S_ + qg], zrow);
  }

  // phase 3: stage E' (pitch 132) + V tile from registers
  #pragma unroll
  for (int j=0;j<2;j++){
    int kl = tx*2 + j;
    ((float4*)&Es[kl*132 + ty*4])[0] =
        make_float4(e[0][j], e[1][j], e[2][j], e[3][j]);
  }
  float4* Vs4 = (float4*)Vs;
  #pragma unroll
  for (int it=0; it<2; it++){
    int i = t + it*512;
    Vs4[i] = vpre[it];
  }
  __syncthreads();

  // phase 4: out[q0:q0+128][:] += E'^T @ V   (4q x 8d per thread, f32x2)
  u64 acc2[4][4];
  #pragma unroll
  for (int i=0;i<4;i++)
    #pragma unroll
    for (int j=0;j<4;j++) acc2[i][j] = 0ull;

  #pragma unroll 2
  for (int k=0;k<32;k++){
    float4 ef = *(const float4*)&Es[k*132 + ty*4];
    const u64* vr = (const u64*)&Vs[k*128 + tx*8];
    u64 v0 = vr[0], v1 = vr[1], v2 = vr[2], v3 = vr[3];
    float ev[4] = {ef.x,ef.y,ef.z,ef.w};
    #pragma unroll
    for (int i=0;i<4;i++){
      u64 e2 = pack2(ev[i], ev[i]);
      acc2[i][0] = fma2(e2, v0, acc2[i][0]);
      acc2[i][1] = fma2(e2, v1, acc2[i][1]);
      acc2[i][2] = fma2(e2, v2, acc2[i][2]);
      acc2[i][3] = fma2(e2, v3, acc2[i][3]);
    }
  }

  #pragma unroll
  for (int i=0;i<4;i++){
    int qg = q0 + ty*4 + i;
    float* op = outp + (b*S_ + qg)*D_ + tx*8;
    float a0,a1,a2,a3,a4,a5,a6,a7;
    unpack2(acc2[i][0],a0,a1);
    unpack2(acc2[i][1],a2,a3);
    unpack2(acc2[i][2],a4,a5);
    unpack2(acc2[i][3],a6,a7);
    atomicAdd((float4*)op,       make_float4(a0,a1,a2,a3));
    atomicAdd((float4*)(op + 4), make_float4(a4,a5,a6,a7));
  }
}

// ---------------- K3: out = (out + totV) / (Z + 1024) --------------------
__global__ void __launch_bounds__(256) k_norm(float* __restrict__ outp){
  int i1 = blockIdx.x*256 + threadIdx.x;   // grid 128 -> 32768 threads
  int i2 = i1 + 32768;
  float4* o4 = (float4*)outp;
  float4 v1 = o4[i1];
  float4 v2 = o4[i2];
  int q1 = i1 >> 5, q2 = i2 >> 5;
  float4 tv1 = ((const float4*)g_totV)[((q1 >> 10) << 5) + (i1 & 31)];
  float4 tv2 = ((const float4*)g_totV)[((q2 >> 10) << 5) + (i2 & 31)];
  float z1 = g_Z[q1], z2 = g_Z[q2];
  float rz1 = 1.f/(z1 + 1024.f), rz2 = 1.f/(z2 + 1024.f);
  v1.x=(v1.x+tv1.x)*rz1; v1.y=(v1.y+tv1.y)*rz1;
  v1.z=(v1.z+tv1.z)*rz1; v1.w=(v1.w+tv1.w)*rz1;
  v2.x=(v2.x+tv2.x)*rz2; v2.y=(v2.y+tv2.y)*rz2;
  v2.z=(v2.z+tv2.z)*rz2; v2.w=(v2.w+tv2.w)*rz2;
  o4[i1] = v1;
  o4[i2] = v2;
}

// ---------------- launch ----------------
extern "C" void kernel_launch(void* const* d_in, const int* in_sizes, int n_in,
                              void* d_out, int out_size){
  (void)in_sizes; (void)n_in; (void)out_size;
  const float* x  = (const float*)d_in[0];
  const float* wq = (const float*)d_in[1];
  const float* bq = (const float*)d_in[2];
  const float* wk = (const float*)d_in[3];
  const float* bk = (const float*)d_in[4];
  const float* wv = (const float*)d_in[5];
  const float* bv = (const float*)d_in[6];
  float* out = (float*)d_out;              // (output, attention_truth)

  const int SMQ = (24576 + 2048) * 4;      // 106,496 B
  const int SMM = 10272 * 4;               // 41,088 B -> 2 blocks/SM
  cudaFuncSetAttribute(k_qkv,  cudaFuncAttributeMaxDynamicSharedMemorySize, SMQ);
  cudaFuncSetAttribute(k_main, cudaFuncAttributeMaxDynamicSharedMemorySize, SMM);

  k_qkv  <<< 128, 512, SMQ >>>(x, wq, bq, wk, bk, wv, bv, out);
  k_main <<< 290, 512, SMM >>>(out);
  k_norm <<< 128, 256 >>>(out);
}